// round 9
// baseline (speedup 1.0000x reference)
#include <cuda_runtime.h>
#include <math.h>

#define BATCH 8
#define SEQ   1024
#define HID   768
#define INNER 64
#define ENT   9
#define NEGC  1000000000000.0f

typedef unsigned long long ull;

// ---------------- f32x2 helpers (FFMA2 path, sm_100+) ----------------
__device__ __forceinline__ ull pack2(float lo, float hi) {
    ull r;
    asm("mov.b64 %0, {%1, %2};" : "=l"(r)
        : "r"(__float_as_uint(lo)), "r"(__float_as_uint(hi)));
    return r;
}
__device__ __forceinline__ ull bcast2(float v) { return pack2(v, v); }
__device__ __forceinline__ void unpack2(ull v, float& lo, float& hi) {
    unsigned int a, b;
    asm("mov.b64 {%0, %1}, %2;" : "=r"(a), "=r"(b) : "l"(v));
    lo = __uint_as_float(a);
    hi = __uint_as_float(b);
}
__device__ __forceinline__ ull ffma2(ull a, ull b, ull c) {
    ull d;
    asm("fma.rn.f32x2 %0, %1, %2, %3;" : "=l"(d) : "l"(a), "l"(b), "l"(c));
    return d;
}

// ---------------- scratch (device globals; no allocation allowed) ----------------
__device__ float g_q[BATCH * SEQ * INNER];       // rope'd q, [row][64]
__device__ float g_k[BATCH * SEQ * INNER];       // rope'd k, [row][64]
__device__ float g_be[BATCH * ENT * SEQ];        // bias even (col/n bias)
__device__ float g_bo[BATCH * ENT * SEQ];        // bias odd  (row/m bias)

// =====================================================================
// Fused Kernel A:
//   blocks 0..127   -> proj GEMM (BM=64, BN=128, BK=16, micro 8x4, FFMA2) + RoPE
//   blocks 128..255 -> bias GEMM (64 rows, k-chunk 32, reg-prefetch double-buffer)
// Dynamic smem = proj layout: (16*68 + 16*128)*4 = 12544 B.
// =====================================================================

__device__ __forceinline__ void proj_body(float* smem,
                                          const float* __restrict__ X,
                                          const float* __restrict__ w1,
                                          const float* __restrict__ b1,
                                          int blk)
{
    float* As = smem;               // [16][68]  (k-major, padded)
    float* Bs = smem + 16 * 68;     // [16][128]

    const int tid = threadIdx.x;
    const int rowBase = blk * 64;

    const int lm = tid >> 2;            // 0..63
    const int lk = (tid & 3) << 2;      // 0,4,8,12
    const float* Xrow = X + (size_t)(rowBase + lm) * HID + lk;

    const int nthr = tid & 31;          // pair index i
    const int mthr = tid >> 5;
    const int n0 = nthr << 2;
    const int m0 = mthr << 3;

    ull acc2[4][4];
#pragma unroll
    for (int mp = 0; mp < 4; ++mp)
#pragma unroll
        for (int ni = 0; ni < 4; ++ni) acc2[mp][ni] = 0ull;

    const int wi0 = tid, wi1 = tid + 256;
    float4 xa  = *(const float4*)(Xrow);
    float4 wv0 = *(const float4*)&w1[(wi0 >> 5) * 128 + (wi0 & 31) * 4];
    float4 wv1 = *(const float4*)&w1[(wi1 >> 5) * 128 + (wi1 & 31) * 4];

    for (int kc = 0; kc < HID / 16; ++kc) {
        __syncthreads();
        As[(lk + 0) * 68 + lm] = xa.x;
        As[(lk + 1) * 68 + lm] = xa.y;
        As[(lk + 2) * 68 + lm] = xa.z;
        As[(lk + 3) * 68 + lm] = xa.w;
        *(float4*)&Bs[(wi0 >> 5) * 128 + (wi0 & 31) * 4] = wv0;
        *(float4*)&Bs[(wi1 >> 5) * 128 + (wi1 & 31) * 4] = wv1;
        __syncthreads();

        if (kc + 1 < HID / 16) {
            xa  = *(const float4*)(Xrow + (kc + 1) * 16);
            wv0 = *(const float4*)&w1[((kc + 1) * 16 + (wi0 >> 5)) * 128 + (wi0 & 31) * 4];
            wv1 = *(const float4*)&w1[((kc + 1) * 16 + (wi1 >> 5)) * 128 + (wi1 & 31) * 4];
        }

#pragma unroll
        for (int kk = 0; kk < 16; ++kk) {
            ulonglong2 A0 = *(const ulonglong2*)(&As[kk * 68 + m0]);
            ulonglong2 A1 = *(const ulonglong2*)(&As[kk * 68 + m0 + 4]);
            float4 bv = *(const float4*)(&Bs[kk * 128 + n0]);
            ull ap[4] = {A0.x, A0.y, A1.x, A1.y};
            ull bb[4] = {bcast2(bv.x), bcast2(bv.y), bcast2(bv.z), bcast2(bv.w)};
#pragma unroll
            for (int mp = 0; mp < 4; ++mp)
#pragma unroll
                for (int ni = 0; ni < 4; ++ni)
                    acc2[mp][ni] = ffma2(ap[mp], bb[ni], acc2[mp][ni]);
        }
    }

    const int i = nthr;
    const float invf = powf(10000.0f, -(float)i * (1.0f / 32.0f));
    const float4 b1v = *(const float4*)&b1[n0];

#pragma unroll
    for (int mp = 0; mp < 4; ++mp) {
        float c0lo, c0hi, c1lo, c1hi, c2lo, c2hi, c3lo, c3hi;
        unpack2(acc2[mp][0], c0lo, c0hi);
        unpack2(acc2[mp][1], c1lo, c1hi);
        unpack2(acc2[mp][2], c2lo, c2hi);
        unpack2(acc2[mp][3], c3lo, c3hi);
        float cA[2][4] = {{c0lo, c1lo, c2lo, c3lo}, {c0hi, c1hi, c2hi, c3hi}};
#pragma unroll
        for (int h = 0; h < 2; ++h) {
            const int r = rowBase + m0 + 2 * mp + h;
            const int pos = r & (SEQ - 1);
            float sv, cv;
            sincosf((float)pos * invf, &sv, &cv);
            const float q0 = cA[h][0] + b1v.x;
            const float k0 = cA[h][1] + b1v.y;
            const float q1 = cA[h][2] + b1v.z;
            const float k1 = cA[h][3] + b1v.w;
            float2 qo = make_float2(fmaf(q0, cv, -q1 * sv), fmaf(q1, cv, q0 * sv));
            float2 ko = make_float2(fmaf(k0, cv, -k1 * sv), fmaf(k1, cv, k0 * sv));
            ((float2*)g_q)[(r << 5) + i] = qo;
            ((float2*)g_k)[(r << 5) + i] = ko;
        }
    }
}

// bias: 64 rows/block, k chunked by 32, register-prefetch double-buffered staging.
// Thread tid = 4*r + s (r = row 0..63, s = k-split 0..3). FFMA2 accumulators (9 pairs).
__device__ __forceinline__ void bias_body(float* smem,
                                          const float* __restrict__ X,
                                          const float* __restrict__ w2,
                                          const float* __restrict__ b2,
                                          int blk)
{
    float* sA = smem;                 // [64][33]
    float* sW = smem + 64 * 33;       // [576] = w2 chunk (32 k x 18 e, contiguous)

    const int tid = threadIdx.x;
    const int r = tid >> 2;           // row in tile
    const int s = tid & 3;            // k-split
    const int rowBase = blk * 64;

    const int rrA = tid >> 3;         // 0..31
    const int j4 = (tid & 7) << 2;    // 0..28

    // prefetch chunk 0
    float4 xA = *(const float4*)&X[(size_t)(rowBase + rrA) * HID + j4];
    float4 xB = *(const float4*)&X[(size_t)(rowBase + 32 + rrA) * HID + j4];
    float4 wF = make_float4(0.f, 0.f, 0.f, 0.f);
    if (tid < 144) wF = *(const float4*)&w2[tid * 4];

    ull acc2[9];
#pragma unroll
    for (int e2 = 0; e2 < 9; ++e2) acc2[e2] = 0ull;

    for (int kc = 0; kc < HID / 32; ++kc) {
        __syncthreads();
        sA[rrA * 33 + j4 + 0] = xA.x;
        sA[rrA * 33 + j4 + 1] = xA.y;
        sA[rrA * 33 + j4 + 2] = xA.z;
        sA[rrA * 33 + j4 + 3] = xA.w;
        sA[(32 + rrA) * 33 + j4 + 0] = xB.x;
        sA[(32 + rrA) * 33 + j4 + 1] = xB.y;
        sA[(32 + rrA) * 33 + j4 + 2] = xB.z;
        sA[(32 + rrA) * 33 + j4 + 3] = xB.w;
        if (tid < 144) *(float4*)&sW[tid * 4] = wF;
        __syncthreads();

        if (kc + 1 < HID / 32) {
            xA = *(const float4*)&X[(size_t)(rowBase + rrA) * HID + (kc + 1) * 32 + j4];
            xB = *(const float4*)&X[(size_t)(rowBase + 32 + rrA) * HID + (kc + 1) * 32 + j4];
            if (tid < 144) wF = *(const float4*)&w2[(kc + 1) * 576 + tid * 4];
        }

#pragma unroll
        for (int kk = 0; kk < 8; ++kk) {
            const ull xb = bcast2(sA[r * 33 + s * 8 + kk]);
            const float* wr = &sW[(s * 8 + kk) * 18];
#pragma unroll
            for (int e2 = 0; e2 < 9; ++e2)
                acc2[e2] = ffma2(xb, *(const ull*)&wr[e2 * 2], acc2[e2]);
        }
    }

    float acc[18];
#pragma unroll
    for (int e2 = 0; e2 < 9; ++e2) unpack2(acc2[e2], acc[2 * e2], acc[2 * e2 + 1]);

#pragma unroll
    for (int e = 0; e < 18; ++e) {
        acc[e] += __shfl_xor_sync(0xffffffffu, acc[e], 1);
        acc[e] += __shfl_xor_sync(0xffffffffu, acc[e], 2);
    }

    if (s == 0) {
        const int row = rowBase + r;
        const int bb = row >> 10, nn = row & (SEQ - 1);
#pragma unroll
        for (int e = 0; e < 18; ++e) {
            const float val = (acc[e] + b2[e]) * 0.5f;
            const int h = e >> 1;
            if ((e & 1) == 0) g_be[(bb * ENT + h) * SEQ + nn] = val;
            else              g_bo[(bb * ENT + h) * SEQ + nn] = val;
        }
    }
}

__global__ __launch_bounds__(256) void k_projbias(const float* __restrict__ X,
                                                  const float* __restrict__ w1,
                                                  const float* __restrict__ b1,
                                                  const float* __restrict__ w2,
                                                  const float* __restrict__ b2)
{
    extern __shared__ __align__(16) float smem[];
    const int bx = blockIdx.x;
    if (bx < 128) proj_body(smem, X, w1, b1, bx);
    else          bias_body(smem, X, w2, b2, bx - 128);
}

// =====================================================================
// Kernel B: out[b,e,m,n] = (qk/8)*mr*mc + (negr*mc + negc + tril) + mr*mc*(be+bo)
// Tile: 128m x 64n, 256 threads, micro-tile 8m x 4n, FFMA2 mainloop.
// 4 CTAs/SM (forced 64-reg budget; mainloop live set ~58 regs fits).
// =====================================================================
__global__ __launch_bounds__(256, 4) void k_out(const float* __restrict__ mask,
                                                float* __restrict__ out)
{
    __shared__ __align__(16) float qt[32 * 132];  // [d][m], stride 132
    __shared__ __align__(16) float kt[32 * 68];   // [d][n], stride 68
    __shared__ __align__(16) float bes[ENT * 64];
    __shared__ __align__(16) float bos[ENT * 128];
    __shared__ __align__(16) float mrow[128];
    __shared__ __align__(16) float mcol[64];

    const int tid = threadIdx.x;
    const int nBase = blockIdx.x * 64;
    const int mBase = blockIdx.y * 128;
    const int b = blockIdx.z;
    const int bOff = b * SEQ;

    const int n0 = (tid & 15) << 2;               // 0..60
    const int m0 = (tid >> 4) << 3;               // 0..120

    for (int i = tid; i < ENT * 64; i += 256)
        bes[i] = g_be[(b * ENT + (i >> 6)) * SEQ + nBase + (i & 63)];
    for (int i = tid; i < ENT * 128; i += 256)
        bos[i] = g_bo[(b * ENT + (i >> 7)) * SEQ + mBase + (i & 127)];
    for (int i = tid; i < 128; i += 256) mrow[i] = mask[b * SEQ + mBase + i];
    if (tid < 64) mcol[tid] = mask[b * SEQ + nBase + tid];

    ull acc2[4][4];
#pragma unroll
    for (int mp = 0; mp < 4; ++mp)
#pragma unroll
        for (int ni = 0; ni < 4; ++ni) acc2[mp][ni] = 0ull;

    for (int ch = 0; ch < 2; ++ch) {
        __syncthreads();
        for (int i = tid; i < 128 * 8; i += 256) {
            int m = i & 127, d4 = (i >> 7) << 2;
            float4 v = *(const float4*)&g_q[((size_t)(bOff + mBase + m) << 6) + ch * 32 + d4];
            qt[(d4 + 0) * 132 + m] = v.x;
            qt[(d4 + 1) * 132 + m] = v.y;
            qt[(d4 + 2) * 132 + m] = v.z;
            qt[(d4 + 3) * 132 + m] = v.w;
        }
        for (int i = tid; i < 64 * 8; i += 256) {
            int n = i & 63, d4 = (i >> 6) << 2;
            float4 v = *(const float4*)&g_k[((size_t)(bOff + nBase + n) << 6) + ch * 32 + d4];
            kt[(d4 + 0) * 68 + n] = v.x;
            kt[(d4 + 1) * 68 + n] = v.y;
            kt[(d4 + 2) * 68 + n] = v.z;
            kt[(d4 + 3) * 68 + n] = v.w;
        }
        __syncthreads();

#pragma unroll 8
        for (int d = 0; d < 32; ++d) {
            float4 kv = *(const float4*)&kt[d * 68 + n0];
            ulonglong2 Q0 = *(const ulonglong2*)&qt[d * 132 + m0];
            ulonglong2 Q1 = *(const ulonglong2*)&qt[d * 132 + m0 + 4];
            ull qp[4] = {Q0.x, Q0.y, Q1.x, Q1.y};
            ull kb[4] = {bcast2(kv.x), bcast2(kv.y), bcast2(kv.z), bcast2(kv.w)};
#pragma unroll
            for (int mp = 0; mp < 4; ++mp)
#pragma unroll
                for (int ni = 0; ni < 4; ++ni)
                    acc2[mp][ni] = ffma2(qp[mp], kb[ni], acc2[mp][ni]);
        }
    }

    float accf[8][4];
#pragma unroll
    for (int mp = 0; mp < 4; ++mp)
#pragma unroll
        for (int ni = 0; ni < 4; ++ni)
            unpack2(acc2[mp][ni], accf[2 * mp][ni], accf[2 * mp + 1][ni]);

    float mr[8];
#pragma unroll
    for (int mi = 0; mi < 8; ++mi) mr[mi] = mrow[m0 + mi];
    float4 mcv = *(const float4*)&mcol[n0];
    float mcs[4] = {mcv.x, mcv.y, mcv.z, mcv.w};

#pragma unroll
    for (int mi = 0; mi < 8; ++mi) {
        const float negr = -NEGC * (1.0f - mr[mi]);
        const int m = mBase + m0 + mi;
#pragma unroll
        for (int ni = 0; ni < 4; ++ni) {
            const float mc = mcs[ni];
            const float negc = -NEGC * (1.0f - mc);
            const int n = nBase + n0 + ni;
            const float t = (n < m) ? -NEGC : 0.0f;
            const float p = accf[mi][ni] * 0.125f * mr[mi];
            accf[mi][ni] = fmaf(p, mc, fmaf(negr, mc, negc + t));
        }
    }

#pragma unroll
    for (int e = 0; e < ENT; ++e) {
        float4 bev = *(const float4*)&bes[e * 64 + n0];
        float beA[4] = {bev.x, bev.y, bev.z, bev.w};
        const size_t planeRow = (size_t)(b * ENT + e) << 10;
#pragma unroll
        for (int mi = 0; mi < 8; ++mi) {
            const float bo = bos[e * 128 + m0 + mi];
            const float c1 = mr[mi] * bo;
            float4 o;
            o.x = fmaf(mcs[0], fmaf(mr[mi], beA[0], c1), accf[mi][0]);
            o.y = fmaf(mcs[1], fmaf(mr[mi], beA[1], c1), accf[mi][1]);
            o.z = fmaf(mcs[2], fmaf(mr[mi], beA[2], c1), accf[mi][2]);
            o.w = fmaf(mcs[3], fmaf(mr[mi], beA[3], c1), accf[mi][3]);
            __stcs((float4*)&out[((planeRow + mBase + m0 + mi) << 10) + nBase + n0], o);
        }
    }
}

// =====================================================================
extern "C" void kernel_launch(void* const* d_in, const int* in_sizes, int n_in,
                              void* d_out, int out_size)
{
    const float* X    = (const float*)d_in[0];   // (8,1024,768)
    const float* mask = (const float*)d_in[1];   // (8,1024)
    const float* w1   = (const float*)d_in[2];   // (768,128)
    const float* b1   = (const float*)d_in[3];   // (128,)
    const float* w2   = (const float*)d_in[4];   // (768,18)
    const float* b2   = (const float*)d_in[5];   // (18,)
    float* out = (float*)d_out;                  // (8,9,1024,1024)

    const int smemBytes = (16 * 68 + 16 * 128) * 4;   // 12544 B
    k_projbias<<<256, 256, smemBytes>>>(X, w1, b1, w2, b2);
    k_out<<<dim3(16, 8, 8), 256>>>(mask, out);
}

// round 11
// speedup vs baseline: 1.1491x; 1.1491x over previous
#include <cuda_runtime.h>
#include <cuda_bf16.h>
#include <math.h>

#define BATCH 8
#define SEQ   1024
#define HID   768
#define INNER 64
#define ENT   9
#define NEGC  1000000000000.0f

typedef unsigned long long ull;
typedef unsigned int uint;

// ---------------- f32x2 helpers (FFMA2 path, sm_100+) ----------------
__device__ __forceinline__ ull pack2(float lo, float hi) {
    ull r;
    asm("mov.b64 %0, {%1, %2};" : "=l"(r)
        : "r"(__float_as_uint(lo)), "r"(__float_as_uint(hi)));
    return r;
}
__device__ __forceinline__ ull bcast2(float v) { return pack2(v, v); }
__device__ __forceinline__ void unpack2(ull v, float& lo, float& hi) {
    uint a, b;
    asm("mov.b64 {%0, %1}, %2;" : "=r"(a), "=r"(b) : "l"(v));
    lo = __uint_as_float(a);
    hi = __uint_as_float(b);
}
__device__ __forceinline__ ull ffma2(ull a, ull b, ull c) {
    ull d;
    asm("fma.rn.f32x2 %0, %1, %2, %3;" : "=l"(d) : "l"(a), "l"(b), "l"(c));
    return d;
}

// ---------------- mma helpers ----------------
__device__ __forceinline__ uint smem_u32(const void* p) {
    return (uint)__cvta_generic_to_shared(p);
}
__device__ __forceinline__ void ldsm_x4(uint& r0, uint& r1, uint& r2, uint& r3, uint addr) {
    asm volatile("ldmatrix.sync.aligned.m8n8.x4.shared.b16 {%0,%1,%2,%3}, [%4];"
                 : "=r"(r0), "=r"(r1), "=r"(r2), "=r"(r3) : "r"(addr));
}
__device__ __forceinline__ void mma_bf16(float* d, uint a0, uint a1, uint a2, uint a3,
                                         uint b0, uint b1) {
    asm volatile("mma.sync.aligned.m16n8k16.row.col.f32.bf16.bf16.f32 "
                 "{%0,%1,%2,%3}, {%4,%5,%6,%7}, {%8,%9}, {%0,%1,%2,%3};"
                 : "+f"(d[0]), "+f"(d[1]), "+f"(d[2]), "+f"(d[3])
                 : "r"(a0), "r"(a1), "r"(a2), "r"(a3), "r"(b0), "r"(b1));
}

// ---------------- scratch (device globals; no allocation allowed) ----------------
__device__ uint g_q[BATCH * SEQ * 32];           // rope'd q, bf16x2 [row][32 pairs]
__device__ uint g_k[BATCH * SEQ * 32];           // rope'd k, bf16x2
__device__ float g_be[BATCH * ENT * SEQ];        // bias even (col/n bias)
__device__ float g_bo[BATCH * ENT * SEQ];        // bias odd  (row/m bias)

// =====================================================================
// Fused Kernel A:
//   blocks 0..127   -> proj GEMM (BM=64, BN=128, BK=16, FFMA2) + RoPE -> bf16
//   blocks 128..255 -> bias GEMM (64 rows, k-chunk 32, reg-prefetch)
// =====================================================================

__device__ __forceinline__ void proj_body(float* smem,
                                          const float* __restrict__ X,
                                          const float* __restrict__ w1,
                                          const float* __restrict__ b1,
                                          int blk)
{
    float* As = smem;               // [16][68]
    float* Bs = smem + 16 * 68;     // [16][128]

    const int tid = threadIdx.x;
    const int rowBase = blk * 64;

    const int lm = tid >> 2;
    const int lk = (tid & 3) << 2;
    const float* Xrow = X + (size_t)(rowBase + lm) * HID + lk;

    const int nthr = tid & 31;          // pair index i
    const int mthr = tid >> 5;
    const int n0 = nthr << 2;
    const int m0 = mthr << 3;

    ull acc2[4][4];
#pragma unroll
    for (int mp = 0; mp < 4; ++mp)
#pragma unroll
        for (int ni = 0; ni < 4; ++ni) acc2[mp][ni] = 0ull;

    const int wi0 = tid, wi1 = tid + 256;
    float4 xa  = *(const float4*)(Xrow);
    float4 wv0 = *(const float4*)&w1[(wi0 >> 5) * 128 + (wi0 & 31) * 4];
    float4 wv1 = *(const float4*)&w1[(wi1 >> 5) * 128 + (wi1 & 31) * 4];

    for (int kc = 0; kc < HID / 16; ++kc) {
        __syncthreads();
        As[(lk + 0) * 68 + lm] = xa.x;
        As[(lk + 1) * 68 + lm] = xa.y;
        As[(lk + 2) * 68 + lm] = xa.z;
        As[(lk + 3) * 68 + lm] = xa.w;
        *(float4*)&Bs[(wi0 >> 5) * 128 + (wi0 & 31) * 4] = wv0;
        *(float4*)&Bs[(wi1 >> 5) * 128 + (wi1 & 31) * 4] = wv1;
        __syncthreads();

        if (kc + 1 < HID / 16) {
            xa  = *(const float4*)(Xrow + (kc + 1) * 16);
            wv0 = *(const float4*)&w1[((kc + 1) * 16 + (wi0 >> 5)) * 128 + (wi0 & 31) * 4];
            wv1 = *(const float4*)&w1[((kc + 1) * 16 + (wi1 >> 5)) * 128 + (wi1 & 31) * 4];
        }

#pragma unroll
        for (int kk = 0; kk < 16; ++kk) {
            ulonglong2 A0 = *(const ulonglong2*)(&As[kk * 68 + m0]);
            ulonglong2 A1 = *(const ulonglong2*)(&As[kk * 68 + m0 + 4]);
            float4 bv = *(const float4*)(&Bs[kk * 128 + n0]);
            ull ap[4] = {A0.x, A0.y, A1.x, A1.y};
            ull bb[4] = {bcast2(bv.x), bcast2(bv.y), bcast2(bv.z), bcast2(bv.w)};
#pragma unroll
            for (int mp = 0; mp < 4; ++mp)
#pragma unroll
                for (int ni = 0; ni < 4; ++ni)
                    acc2[mp][ni] = ffma2(ap[mp], bb[ni], acc2[mp][ni]);
        }
    }

    const int i = nthr;
    const float invf = powf(10000.0f, -(float)i * (1.0f / 32.0f));
    const float4 b1v = *(const float4*)&b1[n0];

#pragma unroll
    for (int mp = 0; mp < 4; ++mp) {
        float c0lo, c0hi, c1lo, c1hi, c2lo, c2hi, c3lo, c3hi;
        unpack2(acc2[mp][0], c0lo, c0hi);
        unpack2(acc2[mp][1], c1lo, c1hi);
        unpack2(acc2[mp][2], c2lo, c2hi);
        unpack2(acc2[mp][3], c3lo, c3hi);
        float cA[2][4] = {{c0lo, c1lo, c2lo, c3lo}, {c0hi, c1hi, c2hi, c3hi}};
#pragma unroll
        for (int h = 0; h < 2; ++h) {
            const int r = rowBase + m0 + 2 * mp + h;
            const int pos = r & (SEQ - 1);
            float sv, cv;
            sincosf((float)pos * invf, &sv, &cv);
            const float q0 = cA[h][0] + b1v.x;
            const float k0 = cA[h][1] + b1v.y;
            const float q1 = cA[h][2] + b1v.z;
            const float k1 = cA[h][3] + b1v.w;
            float2 qo = make_float2(fmaf(q0, cv, -q1 * sv), fmaf(q1, cv, q0 * sv));
            float2 ko = make_float2(fmaf(k0, cv, -k1 * sv), fmaf(k1, cv, k0 * sv));
            __nv_bfloat162 qb = __float22bfloat162_rn(qo);
            __nv_bfloat162 kb = __float22bfloat162_rn(ko);
            g_q[(r << 5) + i] = *(const uint*)&qb;
            g_k[(r << 5) + i] = *(const uint*)&kb;
        }
    }
}

// bias: 64 rows/block, k chunked by 32, register-prefetch double-buffered.
__device__ __forceinline__ void bias_body(float* smem,
                                          const float* __restrict__ X,
                                          const float* __restrict__ w2,
                                          const float* __restrict__ b2,
                                          int blk)
{
    float* sA = smem;                 // [64][33]
    float* sW = smem + 64 * 33;       // [576]

    const int tid = threadIdx.x;
    const int r = tid >> 2;
    const int s = tid & 3;
    const int rowBase = blk * 64;

    const int rrA = tid >> 3;
    const int j4 = (tid & 7) << 2;

    float4 xA = *(const float4*)&X[(size_t)(rowBase + rrA) * HID + j4];
    float4 xB = *(const float4*)&X[(size_t)(rowBase + 32 + rrA) * HID + j4];
    float4 wF = make_float4(0.f, 0.f, 0.f, 0.f);
    if (tid < 144) wF = *(const float4*)&w2[tid * 4];

    ull acc2[9];
#pragma unroll
    for (int e2 = 0; e2 < 9; ++e2) acc2[e2] = 0ull;

    for (int kc = 0; kc < HID / 32; ++kc) {
        __syncthreads();
        sA[rrA * 33 + j4 + 0] = xA.x;
        sA[rrA * 33 + j4 + 1] = xA.y;
        sA[rrA * 33 + j4 + 2] = xA.z;
        sA[rrA * 33 + j4 + 3] = xA.w;
        sA[(32 + rrA) * 33 + j4 + 0] = xB.x;
        sA[(32 + rrA) * 33 + j4 + 1] = xB.y;
        sA[(32 + rrA) * 33 + j4 + 2] = xB.z;
        sA[(32 + rrA) * 33 + j4 + 3] = xB.w;
        if (tid < 144) *(float4*)&sW[tid * 4] = wF;
        __syncthreads();

        if (kc + 1 < HID / 32) {
            xA = *(const float4*)&X[(size_t)(rowBase + rrA) * HID + (kc + 1) * 32 + j4];
            xB = *(const float4*)&X[(size_t)(rowBase + 32 + rrA) * HID + (kc + 1) * 32 + j4];
            if (tid < 144) wF = *(const float4*)&w2[(kc + 1) * 576 + tid * 4];
        }

#pragma unroll
        for (int kk = 0; kk < 8; ++kk) {
            const ull xb = bcast2(sA[r * 33 + s * 8 + kk]);
            const float* wr = &sW[(s * 8 + kk) * 18];
#pragma unroll
            for (int e2 = 0; e2 < 9; ++e2)
                acc2[e2] = ffma2(xb, *(const ull*)&wr[e2 * 2], acc2[e2]);
        }
    }

    float acc[18];
#pragma unroll
    for (int e2 = 0; e2 < 9; ++e2) unpack2(acc2[e2], acc[2 * e2], acc[2 * e2 + 1]);

#pragma unroll
    for (int e = 0; e < 18; ++e) {
        acc[e] += __shfl_xor_sync(0xffffffffu, acc[e], 1);
        acc[e] += __shfl_xor_sync(0xffffffffu, acc[e], 2);
    }

    if (s == 0) {
        const int row = rowBase + r;
        const int bb = row >> 10, nn = row & (SEQ - 1);
#pragma unroll
        for (int e = 0; e < 18; ++e) {
            const float val = (acc[e] + b2[e]) * 0.5f;
            const int h = e >> 1;
            if ((e & 1) == 0) g_be[(bb * ENT + h) * SEQ + nn] = val;
            else              g_bo[(bb * ENT + h) * SEQ + nn] = val;
        }
    }
}

__global__ __launch_bounds__(256) void k_projbias(const float* __restrict__ X,
                                                  const float* __restrict__ w1,
                                                  const float* __restrict__ b1,
                                                  const float* __restrict__ w2,
                                                  const float* __restrict__ b2)
{
    extern __shared__ __align__(16) float smem[];
    const int bx = blockIdx.x;
    if (bx < 128) proj_body(smem, X, w1, b1, bx);
    else          bias_body(smem, X, w2, b2, bx - 128);
}

// =====================================================================
// Kernel B (mma.sync bf16 QK): tile 128m x 64n, 8 warps (warp grid 4m x 2n,
// warp tile 32x32). bf16 tiles padded to 72 elems/row (144B -> conflict-free
// ldmatrix). C frags round-trip through smem so the coalesced float4
// 9-plane epilogue is unchanged.
// =====================================================================
__global__ __launch_bounds__(256) void k_out(const float* __restrict__ mask,
                                             float* __restrict__ out)
{
    __shared__ __align__(16) char region[34816];   // bf16 tiles, then fp32 qk[128][68]
    __shared__ __align__(16) float bes[ENT * 64];
    __shared__ __align__(16) float bos[ENT * 128];
    __shared__ __align__(16) float mrow[128];
    __shared__ __align__(16) float mcol[64];

    const int tid = threadIdx.x;
    const int lane = tid & 31;
    const int wid = tid >> 5;
    const int wm = wid >> 1;                      // 0..3
    const int wn = wid & 1;                       // 0..1
    const int nBase = blockIdx.x * 64;
    const int mBase = blockIdx.y * 128;
    const int b = blockIdx.z;
    const int bOff = b * SEQ;

    const int n0 = (tid & 15) << 2;               // epilogue mapping
    const int m0 = (tid >> 4) << 3;

    // ---- stage aux tiles ----
    for (int i = tid; i < ENT * 64; i += 256)
        bes[i] = g_be[(b * ENT + (i >> 6)) * SEQ + nBase + (i & 63)];
    for (int i = tid; i < ENT * 128; i += 256)
        bos[i] = g_bo[(b * ENT + (i >> 7)) * SEQ + mBase + (i & 127)];
    for (int i = tid; i < 128; i += 256) mrow[i] = mask[b * SEQ + mBase + i];
    if (tid < 64) mcol[tid] = mask[b * SEQ + nBase + tid];

    // ---- stage q (128x64 bf16, row stride 144B) and k (64x64) ----
    {
        const uint4* gq = (const uint4*)g_q;      // 8 uint4 per row
        for (int i = tid; i < 128 * 8; i += 256) {
            int m = i >> 3, c = i & 7;
            uint4 v = gq[(size_t)(bOff + mBase + m) * 8 + c];
            *(uint4*)(region + m * 144 + c * 16) = v;
        }
        const uint4* gk = (const uint4*)g_k;
        for (int i = tid; i < 64 * 8; i += 256) {
            int n = i >> 3, c = i & 7;
            uint4 v = gk[(size_t)(bOff + nBase + n) * 8 + c];
            *(uint4*)(region + 18432 + n * 144 + c * 16) = v;
        }
    }
    __syncthreads();

    // ---- mma mainloop ----
    float acc[2][4][4];
#pragma unroll
    for (int mf = 0; mf < 2; ++mf)
#pragma unroll
        for (int nf = 0; nf < 4; ++nf)
#pragma unroll
            for (int x = 0; x < 4; ++x) acc[mf][nf][x] = 0.f;

    const uint qsm = smem_u32(region);
    const uint ksm = qsm + 18432;
    const uint a_base = qsm + (uint)(wm * 32 + (lane & 15)) * 144 + (uint)(lane >> 4) * 16;
    const uint b_base = ksm + (uint)(wn * 32 + ((lane >> 4) << 3) + (lane & 7)) * 144
                            + (uint)((lane >> 3) & 1) * 16;

#pragma unroll
    for (int ks = 0; ks < 4; ++ks) {
        uint a[2][4], bb[2][4];
#pragma unroll
        for (int mf = 0; mf < 2; ++mf)
            ldsm_x4(a[mf][0], a[mf][1], a[mf][2], a[mf][3], a_base + mf * 2304 + ks * 32);
#pragma unroll
        for (int p = 0; p < 2; ++p)
            ldsm_x4(bb[p][0], bb[p][1], bb[p][2], bb[p][3], b_base + p * 2304 + ks * 32);
#pragma unroll
        for (int mf = 0; mf < 2; ++mf)
#pragma unroll
            for (int p = 0; p < 2; ++p) {
                mma_bf16(acc[mf][2 * p + 0], a[mf][0], a[mf][1], a[mf][2], a[mf][3],
                         bb[p][0], bb[p][1]);
                mma_bf16(acc[mf][2 * p + 1], a[mf][0], a[mf][1], a[mf][2], a[mf][3],
                         bb[p][2], bb[p][3]);
            }
    }

    // ---- C frags -> smem qk[128][68] fp32 ----
    __syncthreads();
    float* qk = (float*)region;
#pragma unroll
    for (int mf = 0; mf < 2; ++mf)
#pragma unroll
        for (int nf = 0; nf < 4; ++nf) {
            int rr = wm * 32 + mf * 16 + (lane >> 2);
            int cc = wn * 32 + nf * 8 + 2 * (lane & 3);
            *(float2*)&qk[rr * 68 + cc]       = make_float2(acc[mf][nf][0], acc[mf][nf][1]);
            *(float2*)&qk[(rr + 8) * 68 + cc] = make_float2(acc[mf][nf][2], acc[mf][nf][3]);
        }
    __syncthreads();

    // ---- epilogue (unchanged math) ----
    float accf[8][4];
#pragma unroll
    for (int mi = 0; mi < 8; ++mi) {
        float4 v = *(const float4*)&qk[(m0 + mi) * 68 + n0];
        accf[mi][0] = v.x; accf[mi][1] = v.y; accf[mi][2] = v.z; accf[mi][3] = v.w;
    }

    float mr[8];
#pragma unroll
    for (int mi = 0; mi < 8; ++mi) mr[mi] = mrow[m0 + mi];
    float4 mcv = *(const float4*)&mcol[n0];
    float mcs[4] = {mcv.x, mcv.y, mcv.z, mcv.w};

#pragma unroll
    for (int mi = 0; mi < 8; ++mi) {
        const float negr = -NEGC * (1.0f - mr[mi]);
        const int m = mBase + m0 + mi;
#pragma unroll
        for (int ni = 0; ni < 4; ++ni) {
            const float mc = mcs[ni];
            const float negc = -NEGC * (1.0f - mc);
            const int n = nBase + n0 + ni;
            const float t = (n < m) ? -NEGC : 0.0f;
            const float p = accf[mi][ni] * 0.125f * mr[mi];
            accf[mi][ni] = fmaf(p, mc, fmaf(negr, mc, negc + t));
        }
    }

#pragma unroll
    for (int e = 0; e < ENT; ++e) {
        float4 bev = *(const float4*)&bes[e * 64 + n0];
        float beA[4] = {bev.x, bev.y, bev.z, bev.w};
        const size_t planeRow = (size_t)(b * ENT + e) << 10;
#pragma unroll
        for (int mi = 0; mi < 8; ++mi) {
            const float bo = bos[e * 128 + m0 + mi];
            const float c1 = mr[mi] * bo;
            float4 o;
            o.x = fmaf(mcs[0], fmaf(mr[mi], beA[0], c1), accf[mi][0]);
            o.y = fmaf(mcs[1], fmaf(mr[mi], beA[1], c1), accf[mi][1]);
            o.z = fmaf(mcs[2], fmaf(mr[mi], beA[2], c1), accf[mi][2]);
            o.w = fmaf(mcs[3], fmaf(mr[mi], beA[3], c1), accf[mi][3]);
            __stcs((float4*)&out[((planeRow + mBase + m0 + mi) << 10) + nBase + n0], o);
        }
    }
}

// =====================================================================
extern "C" void kernel_launch(void* const* d_in, const int* in_sizes, int n_in,
                              void* d_out, int out_size)
{
    const float* X    = (const float*)d_in[0];   // (8,1024,768)
    const float* mask = (const float*)d_in[1];   // (8,1024)
    const float* w1   = (const float*)d_in[2];   // (768,128)
    const float* b1   = (const float*)d_in[3];   // (128,)
    const float* w2   = (const float*)d_in[4];   // (768,18)
    const float* b2   = (const float*)d_in[5];   // (18,)
    float* out = (float*)d_out;                  // (8,9,1024,1024)

    const int smemBytes = (16 * 68 + 16 * 128) * 4;   // 12544 B
    k_projbias<<<256, 256, smemBytes>>>(X, w1, b1, w2, b2);
    k_out<<<dim3(16, 8, 8), 256>>>(mask, out);
}

// round 13
// speedup vs baseline: 1.2302x; 1.0705x over previous
#include <cuda_runtime.h>
#include <cuda_bf16.h>
#include <math.h>

#define BATCH 8
#define SEQ   1024
#define HID   768
#define INNER 64
#define ENT   9
#define NEGC  1000000000000.0f

typedef unsigned long long ull;
typedef unsigned int uint;

// ---------------- f32x2 helpers ----------------
__device__ __forceinline__ ull pack2(float lo, float hi) {
    ull r;
    asm("mov.b64 %0, {%1, %2};" : "=l"(r)
        : "r"(__float_as_uint(lo)), "r"(__float_as_uint(hi)));
    return r;
}
__device__ __forceinline__ ull bcast2(float v) { return pack2(v, v); }
__device__ __forceinline__ void unpack2(ull v, float& lo, float& hi) {
    uint a, b;
    asm("mov.b64 {%0, %1}, %2;" : "=r"(a), "=r"(b) : "l"(v));
    lo = __uint_as_float(a);
    hi = __uint_as_float(b);
}
__device__ __forceinline__ ull ffma2(ull a, ull b, ull c) {
    ull d;
    asm("fma.rn.f32x2 %0, %1, %2, %3;" : "=l"(d) : "l"(a), "l"(b), "l"(c));
    return d;
}

// ---------------- mma helpers ----------------
__device__ __forceinline__ uint smem_u32(const void* p) {
    return (uint)__cvta_generic_to_shared(p);
}
__device__ __forceinline__ void ldsm_x4(uint& r0, uint& r1, uint& r2, uint& r3, uint addr) {
    asm volatile("ldmatrix.sync.aligned.m8n8.x4.shared.b16 {%0,%1,%2,%3}, [%4];"
                 : "=r"(r0), "=r"(r1), "=r"(r2), "=r"(r3) : "r"(addr));
}
__device__ __forceinline__ void mma_bf16(float* d, uint a0, uint a1, uint a2, uint a3,
                                         uint b0, uint b1) {
    asm volatile("mma.sync.aligned.m16n8k16.row.col.f32.bf16.bf16.f32 "
                 "{%0,%1,%2,%3}, {%4,%5,%6,%7}, {%8,%9}, {%0,%1,%2,%3};"
                 : "+f"(d[0]), "+f"(d[1]), "+f"(d[2]), "+f"(d[3])
                 : "r"(a0), "r"(a1), "r"(a2), "r"(a3), "r"(b0), "r"(b1));
}

// ---------------- scratch ----------------
__device__ uint g_q[BATCH * SEQ * 32];           // rope'd q, bf16x2 [row][32 pairs]
__device__ uint g_k[BATCH * SEQ * 32];           // rope'd k, bf16x2
__device__ float g_be[BATCH * ENT * SEQ];        // bias even (col/n bias)
__device__ float g_bo[BATCH * ENT * SEQ];        // bias odd  (row/m bias)

// =====================================================================
// Fused Kernel A:
//   blocks 0..63   -> proj GEMM via bf16 mma (BM=128, N=128, K chunks of 64) + RoPE
//   blocks 64..191 -> bias GEMM (64 rows, k-chunk 32, FFMA2, reg-prefetch)
// Dynamic smem = 36864 B (proj tiles; bias uses a prefix).
// =====================================================================

__device__ __forceinline__ void proj_body(char* region,
                                          const float* __restrict__ X,
                                          const float* __restrict__ w1,
                                          const float* __restrict__ b1,
                                          int blk)
{
    // region layout (mainloop): A = X tile bf16 [128 rows][72] (144B rows) @0
    //                           B = w1^T bf16   [128 nrow][72] @18432
    // after mainloop: reuse @0 as fp32 qk[64][68] per half.
    const int tid = threadIdx.x;
    const int lane = tid & 31;
    const int wid = tid >> 5;
    const int wm = wid >> 1;                 // 0..3 (32 rows each)
    const int wn = wid & 1;                  // 0..1 (64 cols each)
    const int rowBase = blk * 128;

    float acc[2][8][4];
#pragma unroll
    for (int mf = 0; mf < 2; ++mf)
#pragma unroll
        for (int nf = 0; nf < 8; ++nf)
#pragma unroll
            for (int x = 0; x < 4; ++x) acc[mf][nf][x] = 0.f;

    const uint asm_ = smem_u32(region);
    const uint bsm_ = asm_ + 18432;
    const uint a_base = asm_ + (uint)(wm * 32 + (lane & 15)) * 144 + (uint)(lane >> 4) * 16;
    const uint b_base = bsm_ + (uint)(wn * 64 + ((lane >> 4) << 3) + (lane & 7)) * 144
                             + (uint)((lane >> 3) & 1) * 16;

    for (int kc = 0; kc < HID / 64; ++kc) {
        __syncthreads();
        // stage X chunk: 128 rows x 64 k, fp32 -> bf16
        for (int i = tid; i < 2048; i += 256) {
            int row = i >> 4, j = i & 15;
            float4 v = *(const float4*)&X[(size_t)(rowBase + row) * HID + kc * 64 + j * 4];
            __nv_bfloat162 lo = __floats2bfloat162_rn(v.x, v.y);
            __nv_bfloat162 hi = __floats2bfloat162_rn(v.z, v.w);
            uint2 pk = make_uint2(*(const uint*)&lo, *(const uint*)&hi);
            *(uint2*)(region + row * 144 + j * 8) = pk;
        }
        // stage w1^T chunk: read w1[k][n] coalesced, scatter bf16 to [n][k]
        for (int i = tid; i < 8192; i += 256) {
            int kl = i >> 7, n = i & 127;
            float w = w1[(size_t)(kc * 64 + kl) * 128 + n];
            *(__nv_bfloat16*)(region + 18432 + n * 144 + kl * 2) = __float2bfloat16(w);
        }
        __syncthreads();

#pragma unroll
        for (int ks = 0; ks < 4; ++ks) {
            uint a[2][4], bb[4][4];
#pragma unroll
            for (int mf = 0; mf < 2; ++mf)
                ldsm_x4(a[mf][0], a[mf][1], a[mf][2], a[mf][3],
                        a_base + mf * 2304 + ks * 32);
#pragma unroll
            for (int p = 0; p < 4; ++p)
                ldsm_x4(bb[p][0], bb[p][1], bb[p][2], bb[p][3],
                        b_base + p * 2304 + ks * 32);
#pragma unroll
            for (int mf = 0; mf < 2; ++mf)
#pragma unroll
                for (int p = 0; p < 4; ++p) {
                    mma_bf16(acc[mf][2 * p + 0], a[mf][0], a[mf][1], a[mf][2], a[mf][3],
                             bb[p][0], bb[p][1]);
                    mma_bf16(acc[mf][2 * p + 1], a[mf][0], a[mf][1], a[mf][2], a[mf][3],
                             bb[p][2], bb[p][3]);
                }
        }
    }

    // ---- epilogue: two 64-row halves; dump C frags to smem, RoPE from smem ----
    float* qk = (float*)region;              // [64][68] fp32
    const int i = tid & 31;                  // pair index
    const int m0 = (tid >> 5) << 3;          // 8 rows per thread (over 64)
    const float invf = powf(10000.0f, -(float)i * (1.0f / 32.0f));
    const float4 b1v = *(const float4*)&b1[i * 4];

#pragma unroll
    for (int half = 0; half < 2; ++half) {
        __syncthreads();
        if ((wm >> 1) == half) {             // wm 0,1 -> half 0; wm 2,3 -> half 1
            const int rbase = (wm & 1) * 32; // local row base within half
#pragma unroll
            for (int mf = 0; mf < 2; ++mf)
#pragma unroll
                for (int nf = 0; nf < 8; ++nf) {
                    int rr = rbase + mf * 16 + (lane >> 2);
                    int cc = wn * 64 + nf * 8 + 2 * (lane & 3);
                    *(float2*)&qk[rr * 68 + cc]       = make_float2(acc[mf][nf][0], acc[mf][nf][1]);
                    *(float2*)&qk[(rr + 8) * 68 + cc] = make_float2(acc[mf][nf][2], acc[mf][nf][3]);
                }
        }
        __syncthreads();

#pragma unroll
        for (int mi = 0; mi < 8; ++mi) {
            const int lr = m0 + mi;
            const int r = rowBase + half * 64 + lr;
            const int pos = r & (SEQ - 1);
            float sv, cv;
            sincosf((float)pos * invf, &sv, &cv);
            float4 v = *(const float4*)&qk[lr * 68 + i * 4];
            const float q0 = v.x + b1v.x;
            const float k0 = v.y + b1v.y;
            const float q1 = v.z + b1v.z;
            const float k1 = v.w + b1v.w;
            float2 qo = make_float2(fmaf(q0, cv, -q1 * sv), fmaf(q1, cv, q0 * sv));
            float2 ko = make_float2(fmaf(k0, cv, -k1 * sv), fmaf(k1, cv, k0 * sv));
            __nv_bfloat162 qb = __float22bfloat162_rn(qo);
            __nv_bfloat162 kb = __float22bfloat162_rn(ko);
            g_q[(r << 5) + i] = *(const uint*)&qb;
            g_k[(r << 5) + i] = *(const uint*)&kb;
        }
    }
}

// bias: 64 rows/block, k chunked by 32, register-prefetch double-buffered.
__device__ __forceinline__ void bias_body(float* smem,
                                          const float* __restrict__ X,
                                          const float* __restrict__ w2,
                                          const float* __restrict__ b2,
                                          int blk)
{
    float* sA = smem;                 // [64][33]
    float* sW = smem + 64 * 33;       // [576]

    const int tid = threadIdx.x;
    const int r = tid >> 2;
    const int s = tid & 3;
    const int rowBase = blk * 64;

    const int rrA = tid >> 3;
    const int j4 = (tid & 7) << 2;

    float4 xA = *(const float4*)&X[(size_t)(rowBase + rrA) * HID + j4];
    float4 xB = *(const float4*)&X[(size_t)(rowBase + 32 + rrA) * HID + j4];
    float4 wF = make_float4(0.f, 0.f, 0.f, 0.f);
    if (tid < 144) wF = *(const float4*)&w2[tid * 4];

    ull acc2[9];
#pragma unroll
    for (int e2 = 0; e2 < 9; ++e2) acc2[e2] = 0ull;

    for (int kc = 0; kc < HID / 32; ++kc) {
        __syncthreads();
        sA[rrA * 33 + j4 + 0] = xA.x;
        sA[rrA * 33 + j4 + 1] = xA.y;
        sA[rrA * 33 + j4 + 2] = xA.z;
        sA[rrA * 33 + j4 + 3] = xA.w;
        sA[(32 + rrA) * 33 + j4 + 0] = xB.x;
        sA[(32 + rrA) * 33 + j4 + 1] = xB.y;
        sA[(32 + rrA) * 33 + j4 + 2] = xB.z;
        sA[(32 + rrA) * 33 + j4 + 3] = xB.w;
        if (tid < 144) *(float4*)&sW[tid * 4] = wF;
        __syncthreads();

        if (kc + 1 < HID / 32) {
            xA = *(const float4*)&X[(size_t)(rowBase + rrA) * HID + (kc + 1) * 32 + j4];
            xB = *(const float4*)&X[(size_t)(rowBase + 32 + rrA) * HID + (kc + 1) * 32 + j4];
            if (tid < 144) wF = *(const float4*)&w2[(kc + 1) * 576 + tid * 4];
        }

#pragma unroll
        for (int kk = 0; kk < 8; ++kk) {
            const ull xb = bcast2(sA[r * 33 + s * 8 + kk]);
            const float* wr = &sW[(s * 8 + kk) * 18];
#pragma unroll
            for (int e2 = 0; e2 < 9; ++e2)
                acc2[e2] = ffma2(xb, *(const ull*)&wr[e2 * 2], acc2[e2]);
        }
    }

    float acc[18];
#pragma unroll
    for (int e2 = 0; e2 < 9; ++e2) unpack2(acc2[e2], acc[2 * e2], acc[2 * e2 + 1]);

#pragma unroll
    for (int e = 0; e < 18; ++e) {
        acc[e] += __shfl_xor_sync(0xffffffffu, acc[e], 1);
        acc[e] += __shfl_xor_sync(0xffffffffu, acc[e], 2);
    }

    if (s == 0) {
        const int row = rowBase + r;
        const int bb = row >> 10, nn = row & (SEQ - 1);
#pragma unroll
        for (int e = 0; e < 18; ++e) {
            const float val = (acc[e] + b2[e]) * 0.5f;
            const int h = e >> 1;
            if ((e & 1) == 0) g_be[(bb * ENT + h) * SEQ + nn] = val;
            else              g_bo[(bb * ENT + h) * SEQ + nn] = val;
        }
    }
}

__global__ __launch_bounds__(256) void k_projbias(const float* __restrict__ X,
                                                  const float* __restrict__ w1,
                                                  const float* __restrict__ b1,
                                                  const float* __restrict__ w2,
                                                  const float* __restrict__ b2)
{
    extern __shared__ __align__(16) float smem[];
    const int bx = blockIdx.x;
    if (bx < 64) proj_body((char*)smem, X, w1, b1, bx);
    else         bias_body(smem, X, w2, b2, bx - 64);
}

// =====================================================================
// Kernel B (unchanged from R11): mma.sync bf16 QK, tile 128m x 64n.
// =====================================================================
__global__ __launch_bounds__(256) void k_out(const float* __restrict__ mask,
                                             float* __restrict__ out)
{
    __shared__ __align__(16) char region[34816];
    __shared__ __align__(16) float bes[ENT * 64];
    __shared__ __align__(16) float bos[ENT * 128];
    __shared__ __align__(16) float mrow[128];
    __shared__ __align__(16) float mcol[64];

    const int tid = threadIdx.x;
    const int lane = tid & 31;
    const int wid = tid >> 5;
    const int wm = wid >> 1;
    const int wn = wid & 1;
    const int nBase = blockIdx.x * 64;
    const int mBase = blockIdx.y * 128;
    const int b = blockIdx.z;
    const int bOff = b * SEQ;

    const int n0 = (tid & 15) << 2;
    const int m0 = (tid >> 4) << 3;

    for (int i = tid; i < ENT * 64; i += 256)
        bes[i] = g_be[(b * ENT + (i >> 6)) * SEQ + nBase + (i & 63)];
    for (int i = tid; i < ENT * 128; i += 256)
        bos[i] = g_bo[(b * ENT + (i >> 7)) * SEQ + mBase + (i & 127)];
    for (int i = tid; i < 128; i += 256) mrow[i] = mask[b * SEQ + mBase + i];
    if (tid < 64) mcol[tid] = mask[b * SEQ + nBase + tid];

    {
        const uint4* gq = (const uint4*)g_q;
        for (int i = tid; i < 128 * 8; i += 256) {
            int m = i >> 3, c = i & 7;
            uint4 v = gq[(size_t)(bOff + mBase + m) * 8 + c];
            *(uint4*)(region + m * 144 + c * 16) = v;
        }
        const uint4* gk = (const uint4*)g_k;
        for (int i = tid; i < 64 * 8; i += 256) {
            int n = i >> 3, c = i & 7;
            uint4 v = gk[(size_t)(bOff + nBase + n) * 8 + c];
            *(uint4*)(region + 18432 + n * 144 + c * 16) = v;
        }
    }
    __syncthreads();

    float acc[2][4][4];
#pragma unroll
    for (int mf = 0; mf < 2; ++mf)
#pragma unroll
        for (int nf = 0; nf < 4; ++nf)
#pragma unroll
            for (int x = 0; x < 4; ++x) acc[mf][nf][x] = 0.f;

    const uint qsm = smem_u32(region);
    const uint ksm = qsm + 18432;
    const uint a_base = qsm + (uint)(wm * 32 + (lane & 15)) * 144 + (uint)(lane >> 4) * 16;
    const uint b_base = ksm + (uint)(wn * 32 + ((lane >> 4) << 3) + (lane & 7)) * 144
                            + (uint)((lane >> 3) & 1) * 16;

#pragma unroll
    for (int ks = 0; ks < 4; ++ks) {
        uint a[2][4], bb[2][4];
#pragma unroll
        for (int mf = 0; mf < 2; ++mf)
            ldsm_x4(a[mf][0], a[mf][1], a[mf][2], a[mf][3], a_base + mf * 2304 + ks * 32);
#pragma unroll
        for (int p = 0; p < 2; ++p)
            ldsm_x4(bb[p][0], bb[p][1], bb[p][2], bb[p][3], b_base + p * 2304 + ks * 32);
#pragma unroll
        for (int mf = 0; mf < 2; ++mf)
#pragma unroll
            for (int p = 0; p < 2; ++p) {
                mma_bf16(acc[mf][2 * p + 0], a[mf][0], a[mf][1], a[mf][2], a[mf][3],
                         bb[p][0], bb[p][1]);
                mma_bf16(acc[mf][2 * p + 1], a[mf][0], a[mf][1], a[mf][2], a[mf][3],
                         bb[p][2], bb[p][3]);
            }
    }

    __syncthreads();
    float* qk = (float*)region;
#pragma unroll
    for (int mf = 0; mf < 2; ++mf)
#pragma unroll
        for (int nf = 0; nf < 4; ++nf) {
            int rr = wm * 32 + mf * 16 + (lane >> 2);
            int cc = wn * 32 + nf * 8 + 2 * (lane & 3);
            *(float2*)&qk[rr * 68 + cc]       = make_float2(acc[mf][nf][0], acc[mf][nf][1]);
            *(float2*)&qk[(rr + 8) * 68 + cc] = make_float2(acc[mf][nf][2], acc[mf][nf][3]);
        }
    __syncthreads();

    float accf[8][4];
#pragma unroll
    for (int mi = 0; mi < 8; ++mi) {
        float4 v = *(const float4*)&qk[(m0 + mi) * 68 + n0];
        accf[mi][0] = v.x; accf[mi][1] = v.y; accf[mi][2] = v.z; accf[mi][3] = v.w;
    }

    float mr[8];
#pragma unroll
    for (int mi = 0; mi < 8; ++mi) mr[mi] = mrow[m0 + mi];
    float4 mcv = *(const float4*)&mcol[n0];
    float mcs[4] = {mcv.x, mcv.y, mcv.z, mcv.w};

#pragma unroll
    for (int mi = 0; mi < 8; ++mi) {
        const float negr = -NEGC * (1.0f - mr[mi]);
        const int m = mBase + m0 + mi;
#pragma unroll
        for (int ni = 0; ni < 4; ++ni) {
            const float mc = mcs[ni];
            const float negc = -NEGC * (1.0f - mc);
            const int n = nBase + n0 + ni;
            const float t = (n < m) ? -NEGC : 0.0f;
            const float p = accf[mi][ni] * 0.125f * mr[mi];
            accf[mi][ni] = fmaf(p, mc, fmaf(negr, mc, negc + t));
        }
    }

#pragma unroll
    for (int e = 0; e < ENT; ++e) {
        float4 bev = *(const float4*)&bes[e * 64 + n0];
        float beA[4] = {bev.x, bev.y, bev.z, bev.w};
        const size_t planeRow = (size_t)(b * ENT + e) << 10;
#pragma unroll
        for (int mi = 0; mi < 8; ++mi) {
            const float bo = bos[e * 128 + m0 + mi];
            const float c1 = mr[mi] * bo;
            float4 o;
            o.x = fmaf(mcs[0], fmaf(mr[mi], beA[0], c1), accf[mi][0]);
            o.y = fmaf(mcs[1], fmaf(mr[mi], beA[1], c1), accf[mi][1]);
            o.z = fmaf(mcs[2], fmaf(mr[mi], beA[2], c1), accf[mi][2]);
            o.w = fmaf(mcs[3], fmaf(mr[mi], beA[3], c1), accf[mi][3]);
            __stcs((float4*)&out[((planeRow + mBase + m0 + mi) << 10) + nBase + n0], o);
        }
    }
}

// =====================================================================
extern "C" void kernel_launch(void* const* d_in, const int* in_sizes, int n_in,
                              void* d_out, int out_size)
{
    const float* X    = (const float*)d_in[0];   // (8,1024,768)
    const float* mask = (const float*)d_in[1];   // (8,1024)
    const float* w1   = (const float*)d_in[2];   // (768,128)
    const float* b1   = (const float*)d_in[3];   // (128,)
    const float* w2   = (const float*)d_in[4];   // (768,18)
    const float* b2   = (const float*)d_in[5];   // (18,)
    float* out = (float*)d_out;                  // (8,9,1024,1024)

    const int smemBytes = 36864;                 // proj bf16 tiles (bias uses prefix)
    k_projbias<<<192, 256, smemBytes>>>(X, w1, b1, w2, b2);
    k_out<<<dim3(16, 8, 8), 256>>>(mask, out);
}